// round 8
// baseline (speedup 1.0000x reference)
#include <cuda_runtime.h>
#include <cstdint>
#include <math.h>

#define BB   4096
#define SS   50
#define HIDD 256
#define NHH  4
#define HDD  64
#define FBB  26
#define PPER 208   // NH*FB*2

typedef unsigned long long u64;

// ---------------- scratch ----------------
__device__ __align__(16) float g_ctx[BB * HIDD];
__device__ __align__(16) float g_h[BB * HIDD];
__device__ __align__(16) float g_fb[BB * PPER];

// ---------------- helpers ----------------
__device__ __forceinline__ void ffma2(u64 &d, u64 a, u64 b) {
    asm("fma.rn.f32x2 %0, %1, %2, %0;" : "+l"(d) : "l"(a), "l"(b));
}
__device__ __forceinline__ u64 pack2(float lo, float hi) {
    u64 r; asm("mov.b64 %0, {%1, %2};" : "=l"(r) : "f"(lo), "f"(hi)); return r;
}
__device__ __forceinline__ void unpack2(u64 v, float &lo, float &hi) {
    asm("mov.b64 {%0, %1}, %2;" : "=f"(lo), "=f"(hi) : "l"(v));
}
__device__ __forceinline__ float gelu_exact(float x) {
    return 0.5f * x * (1.0f + erff(x * 0.70710678118654752f));
}
__device__ __forceinline__ void cpa16(uint32_t s, const void* g) {
    asm volatile("cp.async.cg.shared.global [%0], [%1], 16;" :: "r"(s), "l"(g));
}
__device__ __forceinline__ void cpa_commit() {
    asm volatile("cp.async.commit_group;");
}
__device__ __forceinline__ void cpa_wait0() {
    asm volatile("cp.async.wait_group 0;" ::: "memory");
}

// ---------------- K1: attr_ctx = mean over S (80% DRAM — at the wall) --------
__global__ __launch_bounds__(256) void k_ctx(const float* __restrict__ attr) {
    int idx = blockIdx.x * 256 + threadIdx.x;
    int b  = idx >> 6;
    int c4 = idx & 63;
    const float4* p = reinterpret_cast<const float4*>(attr + (size_t)b * SS * HIDD) + c4;
    float sx = 0.f, sy = 0.f, sz = 0.f, sw = 0.f;
    #pragma unroll
    for (int t = 0; t < SS; t++) {
        float4 v = p[(size_t)t * (HIDD / 4)];
        sx += v.x; sy += v.y; sz += v.z; sw += v.w;
    }
    float4 o; o.x = sx * 0.02f; o.y = sy * 0.02f; o.z = sz * 0.02f; o.w = sw * 0.02f;
    reinterpret_cast<float4*>(g_ctx)[idx] = o;
}

// ---------------- 64x64x16 tiled GEMMs (register-double-buffered) -------------
#define GPAD 68

__global__ __launch_bounds__(256) void k_g1(const float* __restrict__ w1,
                                            const float* __restrict__ b1) {
    __shared__ float As[16 * GPAD];
    __shared__ float Bs[16 * GPAD];
    int bm0 = blockIdx.x * 64;
    int n0g = blockIdx.y * 64;
    int tid = threadIdx.x;
    int am = tid >> 2, akq = (tid & 3) * 4;
    int bk = tid >> 4, bn  = (tid & 15) * 4;
    int m0 = (tid >> 4) * 4, n0 = (tid & 15) * 4;

    float4 binit = __ldg(reinterpret_cast<const float4*>(b1 + n0g + n0));
    float acc[4][4];
    #pragma unroll
    for (int i = 0; i < 4; i++) {
        acc[i][0] = binit.x; acc[i][1] = binit.y;
        acc[i][2] = binit.z; acc[i][3] = binit.w;
    }

    float4 ra = __ldg(reinterpret_cast<const float4*>(
        g_ctx + (bm0 + am) * HIDD + akq));
    float4 rb = __ldg(reinterpret_cast<const float4*>(
        w1 + bk * HIDD + n0g + bn));

    for (int kt = 0; kt < HIDD; kt += 16) {
        As[(akq + 0) * GPAD + am] = ra.x;
        As[(akq + 1) * GPAD + am] = ra.y;
        As[(akq + 2) * GPAD + am] = ra.z;
        As[(akq + 3) * GPAD + am] = ra.w;
        *reinterpret_cast<float4*>(&Bs[bk * GPAD + bn]) = rb;
        __syncthreads();
        if (kt + 16 < HIDD) {
            ra = __ldg(reinterpret_cast<const float4*>(
                g_ctx + (bm0 + am) * HIDD + kt + 16 + akq));
            rb = __ldg(reinterpret_cast<const float4*>(
                w1 + (kt + 16 + bk) * HIDD + n0g + bn));
        }
        #pragma unroll
        for (int k = 0; k < 16; k++) {
            float4 a4 = *reinterpret_cast<const float4*>(&As[k * GPAD + m0]);
            float4 b4 = *reinterpret_cast<const float4*>(&Bs[k * GPAD + n0]);
            acc[0][0] += a4.x * b4.x; acc[0][1] += a4.x * b4.y;
            acc[0][2] += a4.x * b4.z; acc[0][3] += a4.x * b4.w;
            acc[1][0] += a4.y * b4.x; acc[1][1] += a4.y * b4.y;
            acc[1][2] += a4.y * b4.z; acc[1][3] += a4.y * b4.w;
            acc[2][0] += a4.z * b4.x; acc[2][1] += a4.z * b4.y;
            acc[2][2] += a4.z * b4.z; acc[2][3] += a4.z * b4.w;
            acc[3][0] += a4.w * b4.x; acc[3][1] += a4.w * b4.y;
            acc[3][2] += a4.w * b4.z; acc[3][3] += a4.w * b4.w;
        }
        __syncthreads();
    }
    #pragma unroll
    for (int i = 0; i < 4; i++) {
        float4 o;
        o.x = gelu_exact(acc[i][0]); o.y = gelu_exact(acc[i][1]);
        o.z = gelu_exact(acc[i][2]); o.w = gelu_exact(acc[i][3]);
        *reinterpret_cast<float4*>(&g_h[(bm0 + m0 + i) * HIDD + n0g + n0]) = o;
    }
}

__global__ __launch_bounds__(256) void k_g2(const float* __restrict__ w2,
                                            const float* __restrict__ b2,
                                            const float* __restrict__ bfil,
                                            const float* __restrict__ bbia) {
    __shared__ float As[16 * GPAD];
    __shared__ float Bs[16 * GPAD];
    int bm0 = blockIdx.x * 64;
    int n0g = blockIdx.y * 64;
    int tid = threadIdx.x;
    int am = tid >> 2, akq = (tid & 3) * 4;
    int bk = tid >> 4, bn  = (tid & 15) * 4;
    int m0 = (tid >> 4) * 4, n0 = (tid & 15) * 4;
    int col0 = n0g + n0;
    int bcol = n0g + bn;

    float acc[4][4];
    #pragma unroll
    for (int j = 0; j < 4; j++) {
        float bv = (col0 + j < PPER) ? __ldg(&b2[col0 + j]) : 0.f;
        #pragma unroll
        for (int i = 0; i < 4; i++) acc[i][j] = bv;
    }

    float4 zero4 = make_float4(0.f, 0.f, 0.f, 0.f);
    float4 ra = __ldg(reinterpret_cast<const float4*>(
        g_h + (bm0 + am) * HIDD + akq));
    float4 rb = (bcol < PPER)
        ? __ldg(reinterpret_cast<const float4*>(w2 + bk * PPER + bcol))
        : zero4;

    for (int kt = 0; kt < HIDD; kt += 16) {
        As[(akq + 0) * GPAD + am] = ra.x;
        As[(akq + 1) * GPAD + am] = ra.y;
        As[(akq + 2) * GPAD + am] = ra.z;
        As[(akq + 3) * GPAD + am] = ra.w;
        *reinterpret_cast<float4*>(&Bs[bk * GPAD + bn]) = rb;
        __syncthreads();
        if (kt + 16 < HIDD) {
            ra = __ldg(reinterpret_cast<const float4*>(
                g_h + (bm0 + am) * HIDD + kt + 16 + akq));
            rb = (bcol < PPER)
                ? __ldg(reinterpret_cast<const float4*>(
                      w2 + (kt + 16 + bk) * PPER + bcol))
                : zero4;
        }
        #pragma unroll
        for (int k = 0; k < 16; k++) {
            float4 a4 = *reinterpret_cast<const float4*>(&As[k * GPAD + m0]);
            float4 b4 = *reinterpret_cast<const float4*>(&Bs[k * GPAD + n0]);
            acc[0][0] += a4.x * b4.x; acc[0][1] += a4.x * b4.y;
            acc[0][2] += a4.x * b4.z; acc[0][3] += a4.x * b4.w;
            acc[1][0] += a4.y * b4.x; acc[1][1] += a4.y * b4.y;
            acc[1][2] += a4.y * b4.z; acc[1][3] += a4.y * b4.w;
            acc[2][0] += a4.z * b4.x; acc[2][1] += a4.z * b4.y;
            acc[2][2] += a4.z * b4.z; acc[2][3] += a4.z * b4.w;
            acc[3][0] += a4.w * b4.x; acc[3][1] += a4.w * b4.y;
            acc[3][2] += a4.w * b4.z; acc[3][3] += a4.w * b4.w;
        }
        __syncthreads();
    }
    #pragma unroll
    for (int j = 0; j < 4; j++) {
        int c = col0 + j;
        if (c < PPER) {
            int h = c / 52, rr = c % 52, fi = rr >> 1;
            float basef = __ldg(&bfil[h * FBB + fi]);
            float baseb = __ldg(&bbia[h * FBB + fi]);
            #pragma unroll
            for (int i = 0; i < 4; i++) {
                float v = (rr & 1) ? (baseb + acc[i][j])
                                   : (basef * (1.0f + acc[i][j]));
                g_fb[(bm0 + m0 + i) * PPER + c] = v;
            }
        }
    }
}

// ---------------- k_main helpers (templated, static coeff indexing) ----------
template<int I0, int NI, int PAR>
__device__ __forceinline__ void conv_pass(u64* acc, const float* xcol,
                                          const u64* cdh, int p) {
    u64 cc[13];
    #pragma unroll
    for (int j = 0; j < 13; j++) cc[j] = cdh[2 * j + PAR];
    #pragma unroll
    for (int e = 0; e < 25; e++) {
        int srow = 2 * e + PAR + p;
        if (2 * e + PAR + 1 >= 50) { if (srow >= 50) srow -= 50; }
        u64 xv = *reinterpret_cast<const u64*>(xcol + srow * HIDD);
        #pragma unroll
        for (int i = 0; i < NI; i++) {
            const int dd = ((2 * (I0 + i) - (2 * e + PAR)) % 50 + 50) % 50;
            const int f  = (dd <= 25) ? dd : (50 - dd);
            ffma2(acc[i], xv, cc[f >> 1]);
        }
    }
}

template<int I0, int NI>
__device__ __forceinline__ void acc_init(u64* acc, const float* bvs, int h, int p) {
    #pragma unroll
    for (int i = 0; i < NI; i++) {
        float bv = bvs[h * 50 + 2 * (I0 + i) + p];
        acc[i] = pack2(bv, bv);
    }
}

// cws variant: complex_weight staged in smem (reordered [j][d]), not L1
template<int I0, int NI>
__device__ __forceinline__ void wavelet_combine_s(u64* acc, const float* xs,
                                                  const float* cws,
                                                  int d0, int p) {
    float sgn = p ? -1.0f : 1.0f;
    #pragma unroll
    for (int i = 0; i < NI; i++) {
        int ia = I0 + i;
        float2 e = *reinterpret_cast<const float2*>(&xs[(2 * ia)     * HIDD + d0]);
        float2 o = *reinterpret_cast<const float2*>(&xs[(2 * ia + 1) * HIDD + d0]);
        float2 w = *reinterpret_cast<const float2*>(&cws[ia * HIDD + d0]);
        float ax = 0.5f * (e.x + o.x), ay = 0.5f * (e.y + o.y);
        float dx = 0.5f * (e.x - o.x) * w.x, dy = 0.5f * (e.y - o.y) * w.y;
        float wx = ax + sgn * dx, wy = ay + sgn * dy;
        float ix = p ? o.x : e.x;
        float iy = p ? o.y : e.y;
        float fx, fy; unpack2(acc[i], fx, fy);
        acc[i] = pack2(0.7f * wx + 0.3f * fx + ix,
                       0.7f * wy + 0.3f * fy + iy);
    }
}

template<int I0, int NI>
__device__ __forceinline__ void store_rows(const u64* acc, float* xs, int d0, int p) {
    #pragma unroll
    for (int i = 0; i < NI; i++)
        *reinterpret_cast<u64*>(&xs[(2 * (I0 + i) + p) * HIDD + d0]) = acc[i];
}

// ---------------- K4: persistent 1024-thread, 1 CTA/SM, double-buffered ------
// smem (floats): xs0 0 | xs1 12800 | cws 25600(6400) | fb0 32000(208)
//  | fb1 32208(208) | cd 32416(208) | bvs 32624(200) | ctab 32824(50)
//  | gs 32874(256) | bsv 33130(256)  => 33386 floats = 133544 B
#define SMEM_FLOATS 33386
#define NCTA 148

__device__ __forceinline__ void prefetch_batch(const float* __restrict__ item,
                                               int b, float* xs_s, float* fb_s,
                                               int tid) {
    const float* itemb = item + (size_t)b * SS * HIDD;
    uint32_t xa = (uint32_t)__cvta_generic_to_shared(xs_s);
    for (int i = tid; i < SS * HIDD / 4; i += 1024)
        cpa16(xa + i * 16, itemb + i * 4);
    if (tid < PPER / 4) {
        uint32_t fa = (uint32_t)__cvta_generic_to_shared(fb_s);
        cpa16(fa + tid * 16, g_fb + (size_t)b * PPER + tid * 4);
    }
}

__global__ __launch_bounds__(1024, 1) void k_main(const float* __restrict__ item,
                                                  const float* __restrict__ cw,
                                                  const float* __restrict__ gamma,
                                                  const float* __restrict__ beta,
                                                  float* __restrict__ out) {
    extern __shared__ float sm[];
    float* xsb[2] = { sm,         sm + 12800 };
    float* cws  = sm + 25600;
    float* fbb[2] = { sm + 32000, sm + 32208 };
    float* cd   = sm + 32416;
    float* bvs  = sm + 32624;
    float* ctab = sm + 32824;
    float* gs   = sm + 32874;
    float* bsv  = sm + 33130;

    int tid = threadIdx.x;

    // ---- one-time staging (batch-invariant) ----
    for (int i = tid; i < (SS / 2) * HIDD; i += 1024) {
        int j = i >> 8, d = i & 255, h = d >> 6, dl = d & 63;
        cws[i] = cw[h * (25 * HDD) + j * HDD + dl];
    }
    if (tid < 50)   ctab[tid] = cospif((float)tid * (1.0f / 25.0f));
    if (tid < HIDD) { gs[tid] = gamma[tid]; bsv[tid] = beta[tid]; }

    int b0 = blockIdx.x;
    prefetch_batch(item, b0, xsb[0], fbb[0], tid);
    cpa_commit();

    // ---- thread mapping: tid = rh*256 + p*128 + dp ----
    int dp = tid & 127;
    int p  = (tid >> 7) & 1;
    int rh = tid >> 8;            // 0..3, warp-uniform
    int d0 = dp * 2;
    int h  = dp >> 5;

    int it = 0;
    for (int b = b0; b < BB; b += NCTA, it++) {
        float* xsA = xsb[it & 1];
        float* fbA = fbb[it & 1];

        cpa_wait0();
        __syncthreads();

        int bn = b + NCTA;
        if (bn < BB) prefetch_batch(item, bn, xsb[(it + 1) & 1], fbb[(it + 1) & 1], tid);
        cpa_commit();

        // ---- per-batch circulant coeffs + bias vectors ----
        if (tid < 104) {
            int hh = tid / 26, m = tid % 26;
            const float* fh = fbA + hh * 52;
            float cacc = 0.f;
            int idx = 0;
            #pragma unroll
            for (int k = 0; k < 26; k++) {
                float w = (k == 0 || k == 25) ? 1.0f : 2.0f;
                cacc += fh[2 * k] * w * ctab[idx];
                idx += m; if (idx >= 50) idx -= 50;
            }
            reinterpret_cast<float2*>(cd)[hh * 26 + m] =
                make_float2(cacc * 0.02f, cacc * 0.02f);
        }
        if (tid < 200) {
            int hh = tid / 50, m = tid % 50;
            const float* fh = fbA + hh * 52;
            float bacc = 0.f;
            int idx = 0;
            #pragma unroll
            for (int k = 0; k < 26; k++) {
                float w = (k == 0 || k == 25) ? 1.0f : 2.0f;
                bacc += fh[2 * k + 1] * w * ctab[idx];
                idx += m; if (idx >= 50) idx -= 50;
            }
            bvs[hh * 50 + m] = bacc * 0.14142135623730951f;
        }
        __syncthreads();

        const u64*   cdh  = reinterpret_cast<const u64*>(cd) + h * 26;
        const float* xcol = xsA + d0;

        u64 acc[7];
        if      (rh == 0) { acc_init<0,  7>(acc, bvs, h, p); conv_pass<0,  7, 0>(acc, xcol, cdh, p); }
        else if (rh == 1) { acc_init<7,  6>(acc, bvs, h, p); conv_pass<7,  6, 0>(acc, xcol, cdh, p); }
        else if (rh == 2) { acc_init<13, 6>(acc, bvs, h, p); conv_pass<13, 6, 0>(acc, xcol, cdh, p); }
        else              { acc_init<19, 6>(acc, bvs, h, p); conv_pass<19, 6, 0>(acc, xcol, cdh, p); }
        __syncthreads();   // uniform; scheduling fence between coefficient banks
        if      (rh == 0) conv_pass<0,  7, 1>(acc, xcol, cdh, p);
        else if (rh == 1) conv_pass<7,  6, 1>(acc, xcol, cdh, p);
        else if (rh == 2) conv_pass<13, 6, 1>(acc, xcol, cdh, p);
        else              conv_pass<19, 6, 1>(acc, xcol, cdh, p);

        if      (rh == 0) wavelet_combine_s<0,  7>(acc, xsA, cws, d0, p);
        else if (rh == 1) wavelet_combine_s<7,  6>(acc, xsA, cws, d0, p);
        else if (rh == 2) wavelet_combine_s<13, 6>(acc, xsA, cws, d0, p);
        else              wavelet_combine_s<19, 6>(acc, xsA, cws, d0, p);

        __syncthreads();   // all reads of xsA done
        if      (rh == 0) store_rows<0,  7>(acc, xsA, d0, p);
        else if (rh == 1) store_rows<7,  6>(acc, xsA, d0, p);
        else if (rh == 2) store_rows<13, 6>(acc, xsA, d0, p);
        else              store_rows<19, 6>(acc, xsA, d0, p);
        __syncthreads();

        // ---- LayerNorm: 32 warps over 50 rows ----
        int wid = tid >> 5, lane = tid & 31;
        float* outb = out + (size_t)b * SS * HIDD;
        for (int t = wid; t < SS; t += 32) {
            float v[8];
            float s1 = 0.f, s2 = 0.f;
            #pragma unroll
            for (int q = 0; q < 8; q++) {
                v[q] = xsA[t * HIDD + lane + 32 * q];
                s1 += v[q]; s2 += v[q] * v[q];
            }
            #pragma unroll
            for (int off = 16; off; off >>= 1) {
                s1 += __shfl_xor_sync(0xffffffffu, s1, off);
                s2 += __shfl_xor_sync(0xffffffffu, s2, off);
            }
            float mu  = s1 * (1.0f / 256.0f);
            float var = s2 * (1.0f / 256.0f) - mu * mu;
            float rs  = rsqrtf(var + 1e-12f);
            #pragma unroll
            for (int q = 0; q < 8; q++) {
                int c = lane + 32 * q;
                outb[t * HIDD + c] = (v[q] - mu) * rs * gs[c] + bsv[c];
            }
        }
        __syncthreads();   // xsA fully consumed before it becomes prefetch target
    }
}

// ---------------- launcher ----------------
extern "C" void kernel_launch(void* const* d_in, const int* in_sizes, int n_in,
                              void* d_out, int out_size) {
    const float* item = (const float*)d_in[0];
    const float* attr = (const float*)d_in[1];
    const float* cw   = (const float*)d_in[2];
    const float* bfil = (const float*)d_in[3];
    const float* bbia = (const float*)d_in[4];
    const float* w1   = (const float*)d_in[5];
    const float* b1   = (const float*)d_in[6];
    const float* w2   = (const float*)d_in[7];
    const float* b2   = (const float*)d_in[8];
    const float* gam  = (const float*)d_in[9];
    const float* bet  = (const float*)d_in[10];
    float* out = (float*)d_out;

    cudaFuncSetAttribute(k_main, cudaFuncAttributeMaxDynamicSharedMemorySize,
                         SMEM_FLOATS * (int)sizeof(float));

    k_ctx<<<BB * (HIDD / 4) / 256, 256>>>(attr);
    k_g1<<<dim3(BB / 64, HIDD / 64), 256>>>(w1, b1);
    k_g2<<<dim3(BB / 64, 4), 256>>>(w2, b2, bfil, bbia);
    k_main<<<NCTA, 1024, SMEM_FLOATS * (int)sizeof(float)>>>(item, cw, gam, bet, out);
}

// round 9
// speedup vs baseline: 1.4827x; 1.4827x over previous
#include <cuda_runtime.h>
#include <cstdint>
#include <math.h>

#define BB   4096
#define SS   50
#define HIDD 256
#define NHH  4
#define HDD  64
#define FBB  26
#define PPER 208   // NH*FB*2

typedef unsigned long long u64;

// ---------------- scratch ----------------
__device__ __align__(16) float g_ctx[BB * HIDD];
__device__ __align__(16) float g_h[BB * HIDD];
__device__ __align__(16) float g_fb[BB * PPER];

// ---------------- helpers ----------------
__device__ __forceinline__ void ffma2(u64 &d, u64 a, u64 b) {
    asm("fma.rn.f32x2 %0, %1, %2, %0;" : "+l"(d) : "l"(a), "l"(b));
}
__device__ __forceinline__ u64 pack2(float lo, float hi) {
    u64 r; asm("mov.b64 %0, {%1, %2};" : "=l"(r) : "f"(lo), "f"(hi)); return r;
}
__device__ __forceinline__ void unpack2(u64 v, float &lo, float &hi) {
    asm("mov.b64 {%0, %1}, %2;" : "=f"(lo), "=f"(hi) : "l"(v));
}
__device__ __forceinline__ float gelu_exact(float x) {
    return 0.5f * x * (1.0f + erff(x * 0.70710678118654752f));
}
__device__ __forceinline__ void cpa16(uint32_t s, const void* g) {
    asm volatile("cp.async.cg.shared.global [%0], [%1], 16;" :: "r"(s), "l"(g));
}
__device__ __forceinline__ void cpa_commit() {
    asm volatile("cp.async.commit_group;");
}
__device__ __forceinline__ void cpa_wait0() {
    asm volatile("cp.async.wait_group 0;" ::: "memory");
}

// ---------------- K1: attr_ctx = mean over S (80% DRAM — at the wall) --------
__global__ __launch_bounds__(256) void k_ctx(const float* __restrict__ attr) {
    int idx = blockIdx.x * 256 + threadIdx.x;
    int b  = idx >> 6;
    int c4 = idx & 63;
    const float4* p = reinterpret_cast<const float4*>(attr + (size_t)b * SS * HIDD) + c4;
    float sx = 0.f, sy = 0.f, sz = 0.f, sw = 0.f;
    #pragma unroll
    for (int t = 0; t < SS; t++) {
        float4 v = p[(size_t)t * (HIDD / 4)];
        sx += v.x; sy += v.y; sz += v.z; sw += v.w;
    }
    float4 o; o.x = sx * 0.02f; o.y = sy * 0.02f; o.z = sz * 0.02f; o.w = sw * 0.02f;
    reinterpret_cast<float4*>(g_ctx)[idx] = o;
}

// ---------------- 64x64x16 tiled GEMMs (register-double-buffered) -------------
#define GPAD 68

__global__ __launch_bounds__(256) void k_g1(const float* __restrict__ w1,
                                            const float* __restrict__ b1) {
    __shared__ float As[16 * GPAD];
    __shared__ float Bs[16 * GPAD];
    int bm0 = blockIdx.x * 64;
    int n0g = blockIdx.y * 64;
    int tid = threadIdx.x;
    int am = tid >> 2, akq = (tid & 3) * 4;
    int bk = tid >> 4, bn  = (tid & 15) * 4;
    int m0 = (tid >> 4) * 4, n0 = (tid & 15) * 4;

    float4 binit = __ldg(reinterpret_cast<const float4*>(b1 + n0g + n0));
    float acc[4][4];
    #pragma unroll
    for (int i = 0; i < 4; i++) {
        acc[i][0] = binit.x; acc[i][1] = binit.y;
        acc[i][2] = binit.z; acc[i][3] = binit.w;
    }

    float4 ra = __ldg(reinterpret_cast<const float4*>(
        g_ctx + (bm0 + am) * HIDD + akq));
    float4 rb = __ldg(reinterpret_cast<const float4*>(
        w1 + bk * HIDD + n0g + bn));

    for (int kt = 0; kt < HIDD; kt += 16) {
        As[(akq + 0) * GPAD + am] = ra.x;
        As[(akq + 1) * GPAD + am] = ra.y;
        As[(akq + 2) * GPAD + am] = ra.z;
        As[(akq + 3) * GPAD + am] = ra.w;
        *reinterpret_cast<float4*>(&Bs[bk * GPAD + bn]) = rb;
        __syncthreads();
        if (kt + 16 < HIDD) {
            ra = __ldg(reinterpret_cast<const float4*>(
                g_ctx + (bm0 + am) * HIDD + kt + 16 + akq));
            rb = __ldg(reinterpret_cast<const float4*>(
                w1 + (kt + 16 + bk) * HIDD + n0g + bn));
        }
        #pragma unroll
        for (int k = 0; k < 16; k++) {
            float4 a4 = *reinterpret_cast<const float4*>(&As[k * GPAD + m0]);
            float4 b4 = *reinterpret_cast<const float4*>(&Bs[k * GPAD + n0]);
            acc[0][0] += a4.x * b4.x; acc[0][1] += a4.x * b4.y;
            acc[0][2] += a4.x * b4.z; acc[0][3] += a4.x * b4.w;
            acc[1][0] += a4.y * b4.x; acc[1][1] += a4.y * b4.y;
            acc[1][2] += a4.y * b4.z; acc[1][3] += a4.y * b4.w;
            acc[2][0] += a4.z * b4.x; acc[2][1] += a4.z * b4.y;
            acc[2][2] += a4.z * b4.z; acc[2][3] += a4.z * b4.w;
            acc[3][0] += a4.w * b4.x; acc[3][1] += a4.w * b4.y;
            acc[3][2] += a4.w * b4.z; acc[3][3] += a4.w * b4.w;
        }
        __syncthreads();
    }
    #pragma unroll
    for (int i = 0; i < 4; i++) {
        float4 o;
        o.x = gelu_exact(acc[i][0]); o.y = gelu_exact(acc[i][1]);
        o.z = gelu_exact(acc[i][2]); o.w = gelu_exact(acc[i][3]);
        *reinterpret_cast<float4*>(&g_h[(bm0 + m0 + i) * HIDD + n0g + n0]) = o;
    }
}

__global__ __launch_bounds__(256) void k_g2(const float* __restrict__ w2,
                                            const float* __restrict__ b2,
                                            const float* __restrict__ bfil,
                                            const float* __restrict__ bbia) {
    __shared__ float As[16 * GPAD];
    __shared__ float Bs[16 * GPAD];
    int bm0 = blockIdx.x * 64;
    int n0g = blockIdx.y * 64;
    int tid = threadIdx.x;
    int am = tid >> 2, akq = (tid & 3) * 4;
    int bk = tid >> 4, bn  = (tid & 15) * 4;
    int m0 = (tid >> 4) * 4, n0 = (tid & 15) * 4;
    int col0 = n0g + n0;
    int bcol = n0g + bn;

    float acc[4][4];
    #pragma unroll
    for (int j = 0; j < 4; j++) {
        float bv = (col0 + j < PPER) ? __ldg(&b2[col0 + j]) : 0.f;
        #pragma unroll
        for (int i = 0; i < 4; i++) acc[i][j] = bv;
    }

    float4 zero4 = make_float4(0.f, 0.f, 0.f, 0.f);
    float4 ra = __ldg(reinterpret_cast<const float4*>(
        g_h + (bm0 + am) * HIDD + akq));
    float4 rb = (bcol < PPER)
        ? __ldg(reinterpret_cast<const float4*>(w2 + bk * PPER + bcol))
        : zero4;

    for (int kt = 0; kt < HIDD; kt += 16) {
        As[(akq + 0) * GPAD + am] = ra.x;
        As[(akq + 1) * GPAD + am] = ra.y;
        As[(akq + 2) * GPAD + am] = ra.z;
        As[(akq + 3) * GPAD + am] = ra.w;
        *reinterpret_cast<float4*>(&Bs[bk * GPAD + bn]) = rb;
        __syncthreads();
        if (kt + 16 < HIDD) {
            ra = __ldg(reinterpret_cast<const float4*>(
                g_h + (bm0 + am) * HIDD + kt + 16 + akq));
            rb = (bcol < PPER)
                ? __ldg(reinterpret_cast<const float4*>(
                      w2 + (kt + 16 + bk) * PPER + bcol))
                : zero4;
        }
        #pragma unroll
        for (int k = 0; k < 16; k++) {
            float4 a4 = *reinterpret_cast<const float4*>(&As[k * GPAD + m0]);
            float4 b4 = *reinterpret_cast<const float4*>(&Bs[k * GPAD + n0]);
            acc[0][0] += a4.x * b4.x; acc[0][1] += a4.x * b4.y;
            acc[0][2] += a4.x * b4.z; acc[0][3] += a4.x * b4.w;
            acc[1][0] += a4.y * b4.x; acc[1][1] += a4.y * b4.y;
            acc[1][2] += a4.y * b4.z; acc[1][3] += a4.y * b4.w;
            acc[2][0] += a4.z * b4.x; acc[2][1] += a4.z * b4.y;
            acc[2][2] += a4.z * b4.z; acc[2][3] += a4.z * b4.w;
            acc[3][0] += a4.w * b4.x; acc[3][1] += a4.w * b4.y;
            acc[3][2] += a4.w * b4.z; acc[3][3] += a4.w * b4.w;
        }
        __syncthreads();
    }
    #pragma unroll
    for (int j = 0; j < 4; j++) {
        int c = col0 + j;
        if (c < PPER) {
            int h = c / 52, rr = c % 52, fi = rr >> 1;
            float basef = __ldg(&bfil[h * FBB + fi]);
            float baseb = __ldg(&bbia[h * FBB + fi]);
            #pragma unroll
            for (int i = 0; i < 4; i++) {
                float v = (rr & 1) ? (baseb + acc[i][j])
                                   : (basef * (1.0f + acc[i][j]));
                g_fb[(bm0 + m0 + i) * PPER + c] = v;
            }
        }
    }
}

// ---------------- k_main helpers (templated, static coeff indexing) ----------
template<int I0, int NI, int PAR>
__device__ __forceinline__ void conv_pass(u64* acc, const float* xcol,
                                          const u64* cdh, int p) {
    u64 cc[13];
    #pragma unroll
    for (int j = 0; j < 13; j++) cc[j] = cdh[2 * j + PAR];
    #pragma unroll
    for (int e = 0; e < 25; e++) {
        int srow = 2 * e + PAR + p;
        if (2 * e + PAR + 1 >= 50) { if (srow >= 50) srow -= 50; }
        u64 xv = *reinterpret_cast<const u64*>(xcol + srow * HIDD);
        #pragma unroll
        for (int i = 0; i < NI; i++) {
            const int dd = ((2 * (I0 + i) - (2 * e + PAR)) % 50 + 50) % 50;
            const int f  = (dd <= 25) ? dd : (50 - dd);
            ffma2(acc[i], xv, cc[f >> 1]);
        }
    }
}

template<int I0, int NI>
__device__ __forceinline__ void acc_init(u64* acc, const float* bvs, int h, int p) {
    #pragma unroll
    for (int i = 0; i < NI; i++) {
        float bv = bvs[h * 50 + 2 * (I0 + i) + p];
        acc[i] = pack2(bv, bv);
    }
}

template<int I0, int NI>
__device__ __forceinline__ void wavelet_combine(u64* acc, const float* xs,
                                                const float* __restrict__ cw,
                                                int h, int d0, int p) {
    float sgn = p ? -1.0f : 1.0f;
    int dl = d0 & 63;
    #pragma unroll
    for (int i = 0; i < NI; i++) {
        int ia = I0 + i;
        float2 e = *reinterpret_cast<const float2*>(&xs[(2 * ia)     * HIDD + d0]);
        float2 o = *reinterpret_cast<const float2*>(&xs[(2 * ia + 1) * HIDD + d0]);
        float2 w = __ldg(reinterpret_cast<const float2*>(cw + h * (25 * HDD) + ia * HDD + dl));
        float ax = 0.5f * (e.x + o.x), ay = 0.5f * (e.y + o.y);
        float dx = 0.5f * (e.x - o.x) * w.x, dy = 0.5f * (e.y - o.y) * w.y;
        float wx = ax + sgn * dx, wy = ay + sgn * dy;
        float ix = p ? o.x : e.x;
        float iy = p ? o.y : e.y;
        float fx, fy; unpack2(acc[i], fx, fy);
        acc[i] = pack2(0.7f * wx + 0.3f * fx + ix,
                       0.7f * wy + 0.3f * fy + iy);
    }
}

template<int I0, int NI>
__device__ __forceinline__ void store_rows(const u64* acc, float* xs, int d0, int p) {
    #pragma unroll
    for (int i = 0; i < NI; i++)
        *reinterpret_cast<u64*>(&xs[(2 * (I0 + i) + p) * HIDD + d0]) = acc[i];
}

// ---------------- K4: 512 threads, 2 CTAs/SM (PROVEN structure — grid 4096,
//   smem 56KB keeps complex_weight L1-resident; cp.async stage-in overlaps
//   the coefficient computation) ----------------------------------------------
// smem float offsets: xs 0:12800 | cd 12800:208 | bvs 13008:200 | fbs 13208:208
//                     ctab 13416:50 | gs 13466:256 | bsv 13722:256  => 13978
#define SMEM_FLOATS 13978

__global__ __launch_bounds__(512, 2) void k_main(const float* __restrict__ item,
                                                 const float* __restrict__ cw,
                                                 const float* __restrict__ gamma,
                                                 const float* __restrict__ beta,
                                                 float* __restrict__ out) {
    extern __shared__ float sm[];
    float* xs   = sm;
    float* cd   = sm + 12800;
    float* bvs  = sm + 13008;
    float* fbs  = sm + 13208;
    float* ctab = sm + 13416;
    float* gs   = sm + 13466;
    float* bsv  = sm + 13722;

    int b   = blockIdx.x;
    int tid = threadIdx.x;
    const float* itemb = item + (size_t)b * SS * HIDD;

    // ---- stage: xs via cp.async (latency hidden under coeff compute) ----
    {
        uint32_t xa = (uint32_t)__cvta_generic_to_shared(xs);
        for (int i = tid; i < SS * HIDD / 4; i += 512)
            cpa16(xa + i * 16, itemb + i * 4);
        cpa_commit();
    }
    if (tid < PPER) fbs[tid] = g_fb[b * PPER + tid];
    if (tid < 50)   ctab[tid] = cospif((float)tid * (1.0f / 25.0f));
    if (tid < HIDD) { gs[tid] = gamma[tid]; bsv[tid] = beta[tid]; }
    __syncthreads();   // fbs/ctab visible for coeff compute (xs still in flight)

    // ---- circulant coeffs (even-symmetric, m=0..25, duplicated f32x2) + bias ----
    if (tid < 104) {
        int h = tid / 26, m = tid % 26;
        const float* fh = fbs + h * 52;
        float cacc = 0.f;
        int idx = 0;
        #pragma unroll
        for (int k = 0; k < 26; k++) {
            float w = (k == 0 || k == 25) ? 1.0f : 2.0f;
            cacc += fh[2 * k] * w * ctab[idx];
            idx += m; if (idx >= 50) idx -= 50;
        }
        reinterpret_cast<float2*>(cd)[h * 26 + m] = make_float2(cacc * 0.02f, cacc * 0.02f);
    }
    if (tid < 200) {
        int h = tid / 50, m = tid % 50;
        const float* fh = fbs + h * 52;
        float bacc = 0.f;
        int idx = 0;
        #pragma unroll
        for (int k = 0; k < 26; k++) {
            float w = (k == 0 || k == 25) ? 1.0f : 2.0f;
            bacc += fh[2 * k + 1] * w * ctab[idx];
            idx += m; if (idx >= 50) idx -= 50;
        }
        bvs[h * 50 + m] = bacc * 0.14142135623730951f;
    }
    cpa_wait0();       // xs arrival
    __syncthreads();   // coeffs + xs visible to all

    // ---- thread mapping: tid = rh*256 + p*128 + dp ----
    int dp = tid & 127;
    int p  = (tid >> 7) & 1;
    int rh = tid >> 8;            // warp-uniform
    int d0 = dp * 2;
    int h  = dp >> 5;

    const u64*   cdh  = reinterpret_cast<const u64*>(cd) + h * 26;
    const float* xcol = xs + d0;

    u64 acc[13];
    if (rh == 0) {
        acc_init<0, 13>(acc, bvs, h, p);
        conv_pass<0, 13, 0>(acc, xcol, cdh, p);
    } else {
        acc_init<13, 12>(acc, bvs, h, p);
        conv_pass<13, 12, 0>(acc, xcol, cdh, p);
    }
    __syncthreads();   // uniform; scheduling fence between coefficient banks
    if (rh == 0) conv_pass<0, 13, 1>(acc, xcol, cdh, p);
    else         conv_pass<13, 12, 1>(acc, xcol, cdh, p);

    // ---- wavelet + combine + residual ----
    if (rh == 0) wavelet_combine<0, 13>(acc, xs, cw, h, d0, p);
    else         wavelet_combine<13, 12>(acc, xs, cw, h, d0, p);

    __syncthreads();
    if (rh == 0) store_rows<0, 13>(acc, xs, d0, p);
    else         store_rows<13, 12>(acc, xs, d0, p);
    __syncthreads();

    // ---- LayerNorm: 16 warps over 50 rows ----
    int wid = tid >> 5, lane = tid & 31;
    float* outb = out + (size_t)b * SS * HIDD;
    for (int t = wid; t < SS; t += 16) {
        float v[8];
        float s1 = 0.f, s2 = 0.f;
        #pragma unroll
        for (int q = 0; q < 8; q++) {
            v[q] = xs[t * HIDD + lane + 32 * q];
            s1 += v[q]; s2 += v[q] * v[q];
        }
        #pragma unroll
        for (int off = 16; off; off >>= 1) {
            s1 += __shfl_xor_sync(0xffffffffu, s1, off);
            s2 += __shfl_xor_sync(0xffffffffu, s2, off);
        }
        float mu  = s1 * (1.0f / 256.0f);
        float var = s2 * (1.0f / 256.0f) - mu * mu;
        float rs  = rsqrtf(var + 1e-12f);
        #pragma unroll
        for (int q = 0; q < 8; q++) {
            int c = lane + 32 * q;
            outb[t * HIDD + c] = (v[q] - mu) * rs * gs[c] + bsv[c];
        }
    }
}

// ---------------- launcher ----------------
extern "C" void kernel_launch(void* const* d_in, const int* in_sizes, int n_in,
                              void* d_out, int out_size) {
    const float* item = (const float*)d_in[0];
    const float* attr = (const float*)d_in[1];
    const float* cw   = (const float*)d_in[2];
    const float* bfil = (const float*)d_in[3];
    const float* bbia = (const float*)d_in[4];
    const float* w1   = (const float*)d_in[5];
    const float* b1   = (const float*)d_in[6];
    const float* w2   = (const float*)d_in[7];
    const float* b2   = (const float*)d_in[8];
    const float* gam  = (const float*)d_in[9];
    const float* bet  = (const float*)d_in[10];
    float* out = (float*)d_out;

    cudaFuncSetAttribute(k_main, cudaFuncAttributeMaxDynamicSharedMemorySize,
                         SMEM_FLOATS * (int)sizeof(float));

    k_ctx<<<BB * (HIDD / 4) / 256, 256>>>(attr);
    k_g1<<<dim3(BB / 64, HIDD / 64), 256>>>(w1, b1);
    k_g2<<<dim3(BB / 64, 4), 256>>>(w2, b2, bfil, bbia);
    k_main<<<BB, 512, SMEM_FLOATS * (int)sizeof(float)>>>(item, cw, gam, bet, out);
}